// round 3
// baseline (speedup 1.0000x reference)
#include <cuda_runtime.h>
#include <mma.h>
#include <math.h>

using namespace nvcuda;

#define NB 4
#define NH 16
#define SL 1024
#define DH 64
#define ED 1024
#define MTOT (NB*SL)          // 4096
#define BHN (NB*NH)           // 64

// ---- allocation-free scratch ----
__device__ float g_Q[(size_t)BHN*SL*DH];      // [B,H,L,Dh]
__device__ float g_K[(size_t)BHN*SL*DH];
__device__ float g_V[(size_t)BHN*SL*DH];
__device__ float g_posO[(size_t)MTOT*ED];     // [B,L,E] (head-merged)
__device__ float g_negO[(size_t)MTOT*ED];

// Split a raw fp32 fragment into tf32 hi/lo parts (3xTF32 trick).
template<class Frag>
__device__ __forceinline__ void make_hi_lo(const Frag& raw, Frag& hi, Frag& lo) {
    #pragma unroll
    for (int i = 0; i < raw.num_elements; i++) {
        float v = raw.x[i];
        float h = wmma::__float_to_tf32(v);
        hi.x[i] = h;
        lo.x[i] = wmma::__float_to_tf32(v - h);
    }
}

typedef wmma::fragment<wmma::matrix_a, 16,16,8, wmma::precision::tf32, wmma::row_major> FragA;
typedef wmma::fragment<wmma::matrix_b, 16,16,8, wmma::precision::tf32, wmma::col_major> FragBc;
typedef wmma::fragment<wmma::matrix_b, 16,16,8, wmma::precision::tf32, wmma::row_major> FragBr;
typedef wmma::fragment<wmma::accumulator, 16,16,8, float> FragC;

// ============================================================
// C = A[M,K] @ W[N,K]^T + bias.  M=4096, N=1024, K=1024.
// Block tile 128(M) x 64(N), k-step 16. 8 warps = 4(M) x 2(N),
// each warp 32x32 = 2x2 wmma tiles. Split-TF32 (3 mma per pair).
// SCATTER: write into [B,H,L,Dh] layout.
// ============================================================
template<bool SCATTER>
__global__ __launch_bounds__(256)
void gemm_wmma(const float* __restrict__ A, const float* __restrict__ W,
               const float* __restrict__ bias, float* __restrict__ C)
{
    const int K = 1024;
    __shared__ union SmU {
        struct { float As[128][20]; float Ws[64][20]; } in;
        float Cs[128][68];
    } sm;

    const int t   = threadIdx.x;
    const int wid = t >> 5;
    const int wm  = wid & 3;           // warp row   (x32)
    const int wn  = wid >> 2;          // warp col   (x32)
    const int row0 = blockIdx.y * 128;
    const int col0 = blockIdx.x * 64;

    FragC acc[2][2];
    #pragma unroll
    for (int i = 0; i < 2; i++)
        #pragma unroll
        for (int j = 0; j < 2; j++) wmma::fill_fragment(acc[i][j], 0.f);

    const int ar = t >> 1, ac = (t & 1) * 8;   // A tile: 128 rows x 16 cols
    const int wr = t >> 2, wc = (t & 3) * 4;   // W tile: 64 rows  x 16 cols

    const float* Ap = A + (size_t)(row0 + ar) * K + ac;
    const float* Wp = W + (size_t)(col0 + wr) * K + wc;

    for (int kt = 0; kt < K; kt += 16) {
        float4 a0 = *(const float4*)(Ap + kt);
        float4 a1 = *(const float4*)(Ap + kt + 4);
        float4 w0 = *(const float4*)(Wp + kt);
        __syncthreads();   // all warps done reading previous tiles
        *(float4*)&sm.in.As[ar][ac]     = a0;
        *(float4*)&sm.in.As[ar][ac + 4] = a1;
        *(float4*)&sm.in.Ws[wr][wc]     = w0;
        __syncthreads();

        #pragma unroll
        for (int ks = 0; ks < 16; ks += 8) {
            FragBc braw, bhi[2], blo[2];
            #pragma unroll
            for (int nt = 0; nt < 2; nt++) {
                wmma::load_matrix_sync(braw, &sm.in.Ws[wn*32 + nt*16][ks], 20);
                make_hi_lo(braw, bhi[nt], blo[nt]);
            }
            #pragma unroll
            for (int mt = 0; mt < 2; mt++) {
                FragA araw, ahi, alo;
                wmma::load_matrix_sync(araw, &sm.in.As[wm*32 + mt*16][ks], 20);
                make_hi_lo(araw, ahi, alo);
                #pragma unroll
                for (int nt = 0; nt < 2; nt++) {
                    wmma::mma_sync(acc[mt][nt], ahi, bhi[nt], acc[mt][nt]);
                    wmma::mma_sync(acc[mt][nt], ahi, blo[nt], acc[mt][nt]);
                    wmma::mma_sync(acc[mt][nt], alo, bhi[nt], acc[mt][nt]);
                }
            }
        }
    }
    __syncthreads();   // done with As/Ws before Cs overlays them

    #pragma unroll
    for (int mt = 0; mt < 2; mt++)
        #pragma unroll
        for (int nt = 0; nt < 2; nt++)
            wmma::store_matrix_sync(&sm.Cs[wm*32 + mt*16][wn*32 + nt*16],
                                    acc[mt][nt], 68, wmma::mem_row_major);
    __syncthreads();

    #pragma unroll
    for (int i = 0; i < 32; i++) {
        int idx = i * 256 + t;
        int r = idx >> 6, c = idx & 63;
        int m = row0 + r, n = col0 + c;
        float v = sm.Cs[r][c] + bias[n];
        if (SCATTER) {
            int b = m >> 10, l = m & 1023;
            int h = n >> 6,  d = n & 63;
            C[(((size_t)b*NH + h)*SL + l)*DH + d] = v;
        } else {
            C[(size_t)m * ED + n] = v;
        }
    }
}

// ============================================================
// S[b,h] = Q[b,h] @ K[b,h]^T * 0.125.  64x64 tile, K=64 in smem.
// 8 warps = 4(M of 16) x 2(N of 32). Split-TF32.
// ============================================================
__global__ __launch_bounds__(256)
void scores_wmma(float* __restrict__ S)
{
    __shared__ union SmU {
        struct { float Qs[64][68]; float Ks[64][68]; } in;
        float Ss[64][68];
    } sm;

    const int t   = threadIdx.x;
    const int wid = t >> 5;
    const int wrow = (wid & 3) * 16;   // 0..48
    const int wcol = (wid >> 2) * 32;  // 0 or 32
    const int bh = blockIdx.z;
    const int q0 = blockIdx.y * 64;
    const int k0 = blockIdx.x * 64;
    const float* Qh = g_Q + (size_t)bh * SL * DH;
    const float* Kh = g_K + (size_t)bh * SL * DH;

    // load 64x64 Q and K tiles
    const int r = t >> 2, cb = (t & 3) * 16;
    #pragma unroll
    for (int j = 0; j < 4; j++) {
        float4 q = *(const float4*)(Qh + (size_t)(q0 + r)*DH + cb + j*4);
        float4 k = *(const float4*)(Kh + (size_t)(k0 + r)*DH + cb + j*4);
        *(float4*)&sm.in.Qs[r][cb + j*4] = q;
        *(float4*)&sm.in.Ks[r][cb + j*4] = k;
    }
    __syncthreads();

    FragC acc[2];
    wmma::fill_fragment(acc[0], 0.f);
    wmma::fill_fragment(acc[1], 0.f);

    #pragma unroll
    for (int ks = 0; ks < 64; ks += 8) {
        FragBc braw, bhi[2], blo[2];
        #pragma unroll
        for (int nt = 0; nt < 2; nt++) {
            wmma::load_matrix_sync(braw, &sm.in.Ks[wcol + nt*16][ks], 68);
            make_hi_lo(braw, bhi[nt], blo[nt]);
        }
        FragA araw, ahi, alo;
        wmma::load_matrix_sync(araw, &sm.in.Qs[wrow][ks], 68);
        make_hi_lo(araw, ahi, alo);
        #pragma unroll
        for (int nt = 0; nt < 2; nt++) {
            wmma::mma_sync(acc[nt], ahi, bhi[nt], acc[nt]);
            wmma::mma_sync(acc[nt], ahi, blo[nt], acc[nt]);
            wmma::mma_sync(acc[nt], alo, bhi[nt], acc[nt]);
        }
    }
    __syncthreads();

    #pragma unroll
    for (int nt = 0; nt < 2; nt++) {
        #pragma unroll
        for (int i = 0; i < acc[nt].num_elements; i++) acc[nt].x[i] *= 0.125f;
        wmma::store_matrix_sync(&sm.Ss[wrow][wcol + nt*16], acc[nt], 68, wmma::mem_row_major);
    }
    __syncthreads();

    #pragma unroll
    for (int i = 0; i < 16; i++) {
        int idx = i * 256 + t;
        int rr = idx >> 6, cc = idx & 63;
        S[((size_t)bh * SL + q0 + rr) * SL + k0 + cc] = sm.Ss[rr][cc];
    }
}

// ============================================================
// Per-row softmax + neg-attn (unchanged, memory-bound).
// ============================================================
__global__ void softmax_neg_kernel(float* __restrict__ pos, float* __restrict__ neg)
{
    __shared__ float red[256];
    const int t = threadIdx.x;
    const size_t row = blockIdx.x;
    float* prow = pos + row * SL;
    float* nrow = neg + row * SL;

    float s[4];
    #pragma unroll
    for (int i = 0; i < 4; i++) s[i] = prow[t + i*256];

    float m = fmaxf(fmaxf(s[0], s[1]), fmaxf(s[2], s[3]));
    red[t] = m; __syncthreads();
    for (int o = 128; o > 0; o >>= 1) { if (t < o) red[t] = fmaxf(red[t], red[t+o]); __syncthreads(); }
    m = red[0]; __syncthreads();

    float e[4]; float ls = 0.f;
    #pragma unroll
    for (int i = 0; i < 4; i++) { e[i] = expf(s[i] - m); ls += e[i]; }
    red[t] = ls; __syncthreads();
    for (int o = 128; o > 0; o >>= 1) { if (t < o) red[t] += red[t+o]; __syncthreads(); }
    float invS0 = 1.f / red[0]; __syncthreads();

    float p[4]; float l1 = 0.f;
    #pragma unroll
    for (int i = 0; i < 4; i++) { p[i] = e[i] * invS0; l1 += 1.f - p[i]; }
    red[t] = l1; __syncthreads();
    for (int o = 128; o > 0; o >>= 1) { if (t < o) red[t] += red[t+o]; __syncthreads(); }
    float invS1 = 1.f / red[0]; __syncthreads();

    float tv[4]; float l2 = 0.f;
    #pragma unroll
    for (int i = 0; i < 4; i++) {
        float a  = (1.f - p[i]) * invS1;
        float cb = 1e-6f / (p[i] + 1e-10f);
        tv[i] = fminf(a, cb);
        l2 += tv[i];
    }
    red[t] = l2; __syncthreads();
    for (int o = 128; o > 0; o >>= 1) { if (t < o) red[t] += red[t+o]; __syncthreads(); }
    float invS2 = 1.f / red[0];

    #pragma unroll
    for (int i = 0; i < 4; i++) {
        prow[t + i*256] = p[i];
        nrow[t + i*256] = tv[i] * invS2;
    }
}

// ============================================================
// O[b,h] = P[b,h](1024x1024) @ V[b,h](1024x64) -> [B,L,E] scratch.
// blockIdx.z < 64: pos; else neg. Block tile 128(M) x 64(N), k-step 16.
// 8 warps = 4(M) x 2(N), each 32x32 = 2x2 wmma tiles. Split-TF32.
// ============================================================
__global__ __launch_bounds__(256)
void av_wmma(const float* __restrict__ posA, const float* __restrict__ negA)
{
    __shared__ union SmU {
        struct { float Ps[128][20]; float Vs[16][68]; } in;
        float Cs[128][68];
    } sm;

    const int t   = threadIdx.x;
    const int wid = t >> 5;
    const int wm  = wid & 3;
    const int wn  = wid >> 2;
    const int z = blockIdx.z;
    const bool isPos = (z < BHN);
    const int bh = z & (BHN - 1);
    const float* P  = (isPos ? posA : negA) + (size_t)bh * SL * SL;
    const float* Vh = g_V + (size_t)bh * SL * DH;
    float* dst = isPos ? g_posO : g_negO;
    const int b = bh >> 4, h = bh & 15;
    const int m0 = blockIdx.y * 128;

    FragC acc[2][2];
    #pragma unroll
    for (int i = 0; i < 2; i++)
        #pragma unroll
        for (int j = 0; j < 2; j++) wmma::fill_fragment(acc[i][j], 0.f);

    const int pr = t >> 1, pc = (t & 1) * 8;    // P tile 128x16
    const int vr = t >> 4, vc = (t & 15) * 4;   // V tile 16x64

    for (int k0 = 0; k0 < SL; k0 += 16) {
        float4 p0 = *(const float4*)(P + (size_t)(m0 + pr)*SL + k0 + pc);
        float4 p1 = *(const float4*)(P + (size_t)(m0 + pr)*SL + k0 + pc + 4);
        float4 v0 = *(const float4*)(Vh + (size_t)(k0 + vr)*DH + vc);
        __syncthreads();
        *(float4*)&sm.in.Ps[pr][pc]     = p0;
        *(float4*)&sm.in.Ps[pr][pc + 4] = p1;
        *(float4*)&sm.in.Vs[vr][vc]     = v0;
        __syncthreads();

        #pragma unroll
        for (int ks = 0; ks < 16; ks += 8) {
            FragBr braw, bhi[2], blo[2];
            #pragma unroll
            for (int nt = 0; nt < 2; nt++) {
                wmma::load_matrix_sync(braw, &sm.in.Vs[ks][wn*32 + nt*16], 68);
                make_hi_lo(braw, bhi[nt], blo[nt]);
            }
            #pragma unroll
            for (int mt = 0; mt < 2; mt++) {
                FragA araw, ahi, alo;
                wmma::load_matrix_sync(araw, &sm.in.Ps[wm*32 + mt*16][ks], 20);
                make_hi_lo(araw, ahi, alo);
                #pragma unroll
                for (int nt = 0; nt < 2; nt++) {
                    wmma::mma_sync(acc[mt][nt], ahi, bhi[nt], acc[mt][nt]);
                    wmma::mma_sync(acc[mt][nt], ahi, blo[nt], acc[mt][nt]);
                    wmma::mma_sync(acc[mt][nt], alo, bhi[nt], acc[mt][nt]);
                }
            }
        }
    }
    __syncthreads();

    #pragma unroll
    for (int mt = 0; mt < 2; mt++)
        #pragma unroll
        for (int nt = 0; nt < 2; nt++)
            wmma::store_matrix_sync(&sm.Cs[wm*32 + mt*16][wn*32 + nt*16],
                                    acc[mt][nt], 68, wmma::mem_row_major);
    __syncthreads();

    #pragma unroll
    for (int i = 0; i < 32; i++) {
        int idx = i * 256 + t;
        int r = idx >> 6, c = idx & 63;
        dst[((size_t)b*SL + m0 + r) * ED + (size_t)h*DH + c] = sm.Cs[r][c];
    }
}

// ============================================================
extern "C" void kernel_launch(void* const* d_in, const int* in_sizes, int n_in,
                              void* d_out, int out_size)
{
    const float* query = (const float*)d_in[0];
    const float* key   = (const float*)d_in[1];
    const float* value = (const float*)d_in[2];
    const float* Wq = (const float*)d_in[3];
    const float* bq = (const float*)d_in[4];
    const float* Wk = (const float*)d_in[5];
    const float* bk = (const float*)d_in[6];
    const float* Wv = (const float*)d_in[7];
    const float* bv = (const float*)d_in[8];
    const float* Wo = (const float*)d_in[9];
    const float* bo = (const float*)d_in[10];

    float* out = (float*)d_out;
    float* pos_output = out;
    float* neg_output = out + (size_t)MTOT * ED;
    float* pos_attn   = out + (size_t)2 * MTOT * ED;
    float* neg_attn   = pos_attn + (size_t)BHN * SL * SL;

    float *Qp, *Kp, *Vp, *pOp, *nOp;
    cudaGetSymbolAddress((void**)&Qp,  g_Q);
    cudaGetSymbolAddress((void**)&Kp,  g_K);
    cudaGetSymbolAddress((void**)&Vp,  g_V);
    cudaGetSymbolAddress((void**)&pOp, g_posO);
    cudaGetSymbolAddress((void**)&nOp, g_negO);

    dim3 gemmGrid(ED/64, MTOT/128);   // (16, 32)

    // Projections -> [B,H,L,Dh]
    gemm_wmma<true><<<gemmGrid, 256>>>(query, Wq, bq, Qp);
    gemm_wmma<true><<<gemmGrid, 256>>>(key,   Wk, bk, Kp);
    gemm_wmma<true><<<gemmGrid, 256>>>(value, Wv, bv, Vp);

    // Raw scaled scores into pos_attn region
    scores_wmma<<<dim3(SL/64, SL/64, BHN), 256>>>(pos_attn);

    // In-place softmax + neg-attn
    softmax_neg_kernel<<<BHN * SL, 256>>>(pos_attn, neg_attn);

    // attn @ V for pos and neg -> [B,L,E] scratch
    av_wmma<<<dim3(1, SL/128, 2*BHN), 256>>>(pos_attn, neg_attn);

    // Output projections
    gemm_wmma<false><<<gemmGrid, 256>>>(pOp, Wo, bo, pos_output);
    gemm_wmma<false><<<gemmGrid, 256>>>(nOp, Wo, bo, neg_output);
}